// round 7
// baseline (speedup 1.0000x reference)
#include <cuda_runtime.h>
#include <cuda_bf16.h>
#include <cstdint>

// Problem constants (fixed by reference):
//   g: (32, 16, 2048, 3) fp32, ar_phi: (3,3), ar_eta: (3,), ar_c: (3,)
//   P=3, KMAX=5 (11 windings), output: (32,) fp32
#define N_MC      32
#define N_SAMP    16
#define N_ROWS    (N_MC * N_SAMP)       // 512
#define T_LEN     2048
#define TPRIME    2044                   // T - 1 - P
#define ROW_ELEMS (T_LEN * 3)            // 6144 floats
#define ROW_VEC4  (ROW_ELEMS / 4)        // 1536 float4s per row

#define BLOCK     128
#define CHUNK     16                     // t-outputs per thread (128*16 = 2048)
#define NLD       15                     // float4 loads per thread (20 angles x 3 dims)

#define PI_F      3.14159265358979323846f
#define TWO_PI_F  6.28318530717958647693f
#define INV_2PI_F 0.15915494309189533577f

// Deterministic scratch: per-row fp32 partial sums (xyz = per-dim sum of u^2),
// fully overwritten every launch. No atomics, no fences anywhere.
__device__ float4 g_part[N_ROWS];

// Torus logmap, cheap form: x - 2*pi*rint(x/2pi). Matches mod(x+pi,2pi)-pi
// except at exact half-period boundaries (measure zero in fp32 data).
__device__ __forceinline__ float wrapf(float x) {
    return fmaf(-rintf(x * INV_2PI_F), TWO_PI_F, x);
}

__global__ __launch_bounds__(BLOCK)
void arp_row_kernel(const float* __restrict__ g,
                    const float* __restrict__ ar_phi,
                    const float* __restrict__ ar_c) {
    __shared__ float sred[3][BLOCK / 32];

    const int tid = threadIdx.x;
    const int row = blockIdx.x;          // (m*16 + s)

    // Small params (L1-cached broadcast loads).
    float ph[3][3], cc[3];
#pragma unroll
    for (int d = 0; d < 3; d++) {
        ph[d][0] = __ldg(&ar_phi[d * 3 + 0]);
        ph[d][1] = __ldg(&ar_phi[d * 3 + 1]);
        ph[d][2] = __ldg(&ar_phi[d * 3 + 2]);
        cc[d]    = __ldg(&ar_c[d]);
    }

    // ---- Front-batched vectorized load: angles t0..t0+19, all 3 dims
    // = 60 floats = 15 consecutive float4s (3*t0 = 48*tid divisible by 4).
    // Warp footprint contiguous -> fully coalesced; max MLP per warp.
    const int t0   = tid * CHUNK;
    const int base = 12 * tid;           // (3*t0)/4
    const float4* g4 = reinterpret_cast<const float4*>(g)
                     + (size_t)row * ROW_VEC4;
    float f[4 * NLD];
#pragma unroll
    for (int k = 0; k < NLD; k++) {
        int idx = base + k;
        if (idx > ROW_VEC4 - 1) idx = ROW_VEC4 - 1;   // tail clamp (unused data)
        float4 v = __ldg(&g4[idx]);
        f[4 * k + 0] = v.x; f[4 * k + 1] = v.y;
        f[4 * k + 2] = v.z; f[4 * k + 3] = v.w;
    }

    // ---- AR(3) on wrapped first-diffs; each dx computed exactly once.
    float acc[3];
#pragma unroll
    for (int d = 0; d < 3; d++) {
        float dx[CHUNK + 3];
#pragma unroll
        for (int j = 0; j < CHUNK + 3; j++)
            dx[j] = wrapf(f[3 * (j + 1) + d] - f[3 * j + d]);
        float ss = 0.f;
#pragma unroll
        for (int j = 0; j < CHUNK; j++) {
            float dyv = dx[j + 3] - (ph[d][0] * dx[j + 2]
                                   + ph[d][1] * dx[j + 1]
                                   + ph[d][2] * dx[j]);
            float u = dyv - cc[d];
            if (t0 + j < TPRIME) ss = fmaf(u, u, ss);
        }
        acc[d] = ss;
    }

    // ---- Warp reduce, then 4-warp fold; single fp32 float4 store. No sync
    // beyond one __syncthreads; kernel boundary orders K1 stores before K2.
#pragma unroll
    for (int off = 16; off; off >>= 1)
#pragma unroll
        for (int d = 0; d < 3; d++)
            acc[d] += __shfl_xor_sync(0xffffffffu, acc[d], off);

    const int lane = tid & 31;
    const int warp = tid >> 5;
    if (lane == 0)
#pragma unroll
        for (int d = 0; d < 3; d++) sred[d][warp] = acc[d];
    __syncthreads();

    if (tid == 0) {
        float4 p;
        p.x = sred[0][0] + sred[0][1] + sred[0][2] + sred[0][3];
        p.y = sred[1][0] + sred[1][1] + sred[1][2] + sred[1][3];
        p.z = sred[2][0] + sred[2][1] + sred[2][2] + sred[2][3];
        p.w = 0.f;
        g_part[row] = p;
    }
}

__global__ void arp_final_kernel(const float* __restrict__ ar_eta,
                                 float* __restrict__ out) {
    const int m = threadIdx.x;
    if (m >= N_MC) return;

    float S[3] = {0.f, 0.f, 0.f};
#pragma unroll
    for (int s = 0; s < N_SAMP; s++) {
        float4 p = g_part[m * N_SAMP + s];
        S[0] += p.x; S[1] += p.y; S[2] += p.z;
    }

    // sum_{k=-5..5} winding log-density collapses (sum k = 0, sum k^2 = 110)
    // per (t,d) to: -5.5*u^2/var - 220*pi^2/var - 11*log(e) - 5.5*log(2*pi).
    // fp32 throughout: abs error ~1e4 vs tolerance budget ~8.5e7.
    float res = 0.f;
#pragma unroll
    for (int d = 0; d < 3; d++) {
        float e   = fabsf(__ldg(&ar_eta[d]));   // scale = sqrt(eta^2)
        float var = e * e;
        float C = -220.f * (PI_F * PI_F) / var - 11.f * logf(e)
                  - 5.5f * logf(TWO_PI_F);
        res += -5.5f * S[d] / var + (float)(N_SAMP * TPRIME) * C;
    }
    out[m] = res;
}

extern "C" void kernel_launch(void* const* d_in, const int* in_sizes, int n_in,
                              void* d_out, int out_size) {
    const float* g      = (const float*)d_in[0];
    const float* ar_phi = (const float*)d_in[1];
    const float* ar_eta = (const float*)d_in[2];
    const float* ar_c   = (const float*)d_in[3];
    float* out = (float*)d_out;

    arp_row_kernel<<<N_ROWS, BLOCK>>>(g, ar_phi, ar_c);
    arp_final_kernel<<<1, 32>>>(ar_eta, out);
}

// round 8
// speedup vs baseline: 1.1843x; 1.1843x over previous
#include <cuda_runtime.h>
#include <cuda_bf16.h>
#include <cstdint>

// Problem constants (fixed by reference):
//   g: (32, 16, 2048, 3) fp32, ar_phi: (3,3), ar_eta: (3,), ar_c: (3,)
//   P=3, KMAX=5 (11 windings), output: (32,) fp32
#define N_MC      32
#define N_SAMP    16
#define T_LEN     2048
#define TPRIME    2044                   // T - 1 - P
#define ROW_ELEMS (T_LEN * 3)            // 6144 floats
#define ROW_VEC4  (ROW_ELEMS / 4)        // 1536 float4s per row

#define CLUSTER   8                      // CTAs per cluster = per output m
#define SPC       2                      // samples per CTA (8*2 = 16 = N_SAMP)
#define GRID      (N_MC * CLUSTER)       // 256 CTAs, single wave
#define BLOCK     256
#define CHUNK     8                      // t-outputs per thread per sample

#define PI_F      3.14159265358979323846f
#define TWO_PI_F  6.28318530717958647693f
#define INV_2PI_F 0.15915494309189533577f
#define MAGIC_F   12582912.0f            // 1.5 * 2^23

// Torus logmap with NO conversion-pipe ops: round-to-nearest via the
// magic-number trick (valid: |x/2pi| < 2.2 << 2^22). All fma-pipe, lat 4.
//   k = rint(x/2pi);  wrap = x - 2pi*k
// Matches mod(x+pi,2pi)-pi except exact half-period boundaries (measure zero).
__device__ __forceinline__ float wrapf(float x) {
    float y = fmaf(x, INV_2PI_F, MAGIC_F);   // exact-r + magic, RN -> integer
    float k = __fadd_rn(y, -MAGIC_F);        // keep as separate FADD (no fuse)
    return fmaf(-k, TWO_PI_F, x);
}

__device__ __forceinline__ uint32_t smem_u32(const void* p) {
    uint32_t a;
    asm("{ .reg .u64 t; cvta.to.shared.u64 t, %1; cvt.u32.u64 %0, t; }"
        : "=r"(a) : "l"(p));
    return a;
}

__global__ __launch_bounds__(BLOCK) __cluster_dims__(CLUSTER, 1, 1)
void arp_cluster_kernel(const float* __restrict__ g,
                        const float* __restrict__ ar_phi,
                        const float* __restrict__ ar_eta,
                        const float* __restrict__ ar_c,
                        float* __restrict__ out) {
    __shared__ float sred[3][BLOCK / 32];
    __shared__ float slots[CLUSTER][3];   // leader CTA collects per-rank sums

    const int tid = threadIdx.x;
    const int m   = blockIdx.x / CLUSTER;
    uint32_t rank;
    asm("mov.u32 %0, %%cluster_ctarank;" : "=r"(rank));

    // Small params (L1-cached broadcast loads).
    float ph[3][3], cc[3];
#pragma unroll
    for (int d = 0; d < 3; d++) {
        ph[d][0] = __ldg(&ar_phi[d * 3 + 0]);
        ph[d][1] = __ldg(&ar_phi[d * 3 + 1]);
        ph[d][2] = __ldg(&ar_phi[d * 3 + 2]);
        cc[d]    = __ldg(&ar_c[d]);
    }

    const int t0   = tid * CHUNK;
    const int base = (3 * t0) >> 2;          // 3*t0 divisible by 4 (t0 % 8 == 0)
    const bool full = (t0 + CHUNK <= TPRIME); // false only for tid 255

    // ---- Two sample-rows per CTA: direct vectorized loads, AR(3) on wrapped
    // first-diffs (each dx computed exactly once), fp32 accumulation.
    float acc[3] = {0.f, 0.f, 0.f};
#pragma unroll
    for (int s = 0; s < SPC; s++) {
        const int row = m * N_SAMP + (int)rank * SPC + s;
        const float4* g4 = reinterpret_cast<const float4*>(g)
                         + (size_t)row * ROW_VEC4;
        float f[36];
#pragma unroll
        for (int k = 0; k < 9; k++) {
            int idx = base + k;
            if (idx > ROW_VEC4 - 1) idx = ROW_VEC4 - 1;   // tail clamp (unused)
            float4 v = __ldg(&g4[idx]);
            f[4 * k + 0] = v.x; f[4 * k + 1] = v.y;
            f[4 * k + 2] = v.z; f[4 * k + 3] = v.w;
        }
#pragma unroll
        for (int d = 0; d < 3; d++) {
            float dx[CHUNK + 3];
#pragma unroll
            for (int j = 0; j < CHUNK + 3; j++)
                dx[j] = wrapf(f[3 * (j + 1) + d] - f[3 * j + d]);
            float ss = 0.f;
            if (full) {
#pragma unroll
                for (int j = 0; j < CHUNK; j++) {
                    float dyv = dx[j + 3] - (ph[d][0] * dx[j + 2]
                                           + ph[d][1] * dx[j + 1]
                                           + ph[d][2] * dx[j]);
                    float u = dyv - cc[d];
                    ss = fmaf(u, u, ss);
                }
            } else {
#pragma unroll
                for (int j = 0; j < CHUNK; j++) {
                    float dyv = dx[j + 3] - (ph[d][0] * dx[j + 2]
                                           + ph[d][1] * dx[j + 1]
                                           + ph[d][2] * dx[j]);
                    float u = dyv - cc[d];
                    if (t0 + j < TPRIME) ss = fmaf(u, u, ss);
                }
            }
            acc[d] += ss;
        }
    }

    // ---- Warp reduce, then 8-warp fold.
#pragma unroll
    for (int off = 16; off; off >>= 1)
#pragma unroll
        for (int d = 0; d < 3; d++)
            acc[d] += __shfl_xor_sync(0xffffffffu, acc[d], off);

    const int lane = tid & 31;
    const int warp = tid >> 5;
    if (lane == 0)
#pragma unroll
        for (int d = 0; d < 3; d++) sred[d][warp] = acc[d];
    __syncthreads();

    // ---- tid0 pushes this CTA's 3 sums into the LEADER CTA's slots via DSMEM.
    if (tid == 0) {
        float S[3];
#pragma unroll
        for (int d = 0; d < 3; d++) {
            float v = sred[d][0];
#pragma unroll
            for (int w = 1; w < BLOCK / 32; w++) v += sred[d][w];
            S[d] = v;
        }
        uint32_t laddr = smem_u32(&slots[rank][0]);   // same layout in every CTA
        uint32_t raddr;
        asm volatile("mapa.shared::cluster.u32 %0, %1, %2;"
                     : "=r"(raddr) : "r"(laddr), "r"(0u));   // -> leader (rank 0)
#pragma unroll
        for (int d = 0; d < 3; d++)
            asm volatile("st.shared::cluster.f32 [%0], %1;"
                         :: "r"(raddr + 4u * d), "f"(S[d]) : "memory");
    }

    // Cluster barrier: release DSMEM stores, then leader may read.
    asm volatile("barrier.cluster.arrive.aligned;" ::: "memory");
    asm volatile("barrier.cluster.wait.aligned;" ::: "memory");

    // ---- Leader CTA: fold 8 ranks + closed-form winding constant, write out[m].
    //   sum_{k=-5..5} winding log-density collapses (sum k = 0, sum k^2 = 110)
    //   per (t,d) to: -5.5*u^2/var - 220*pi^2/var - 11*log(e) - 5.5*log(2*pi).
    // fp32 throughout: abs error ~1e4 vs tolerance budget ~8.5e7.
    if (rank == 0 && tid == 0) {
        float res = 0.f;
#pragma unroll
        for (int d = 0; d < 3; d++) {
            float Sd = 0.f;
#pragma unroll
            for (int r = 0; r < CLUSTER; r++) Sd += slots[r][d];
            float e   = fabsf(ar_eta[d]);            // scale = sqrt(eta^2)
            float var = e * e;
            float C = -220.f * (PI_F * PI_F) / var - 11.f * logf(e)
                      - 5.5f * logf(TWO_PI_F);
            res += -5.5f * Sd / var + (float)(N_SAMP * TPRIME) * C;
        }
        out[m] = res;
    }
}

extern "C" void kernel_launch(void* const* d_in, const int* in_sizes, int n_in,
                              void* d_out, int out_size) {
    const float* g      = (const float*)d_in[0];
    const float* ar_phi = (const float*)d_in[1];
    const float* ar_eta = (const float*)d_in[2];
    const float* ar_c   = (const float*)d_in[3];
    float* out = (float*)d_out;

    arp_cluster_kernel<<<GRID, BLOCK>>>(g, ar_phi, ar_eta, ar_c, out);
}

// round 9
// speedup vs baseline: 1.2393x; 1.0464x over previous
#include <cuda_runtime.h>
#include <cuda_bf16.h>
#include <cstdint>

// Problem constants (fixed by reference):
//   g: (32, 16, 2048, 3) fp32, ar_phi: (3,3), ar_eta: (3,), ar_c: (3,)
//   P=3, KMAX=5 (11 windings), output: (32,) fp32
#define N_MC      32
#define N_SAMP    16
#define T_LEN     2048
#define TPRIME    2044                   // T - 1 - P
#define ROW_ELEMS (T_LEN * 3)            // 6144 floats
#define ROW_VEC4  (ROW_ELEMS / 4)        // 1536 float4s per row
#define ROW_BYTES (ROW_ELEMS * 4)        // 24576

#define CLUSTER   8                      // CTAs per cluster = per output m
#define SPC       2                      // samples per CTA (8*2 = 16 = N_SAMP)
#define GRID      (N_MC * CLUSTER)       // 256 CTAs, single wave
#define BLOCK     256
#define CHUNK     8                      // t-outputs per thread per sample

#define STAGE_BYTES (SPC * ROW_BYTES)    // 49152: one bulk copy per CTA
// Dynamic SMEM layout: [staging 49152B][sred 96B][slots 96B][mbar 8B]
#define OFF_SRED  STAGE_BYTES
#define OFF_SLOTS (OFF_SRED + 96)
#define OFF_MBAR  (OFF_SLOTS + 96)
#define SMEM_TOTAL (OFF_MBAR + 16)

#define PI_F      3.14159265358979323846f
#define TWO_PI_F  6.28318530717958647693f
#define INV_2PI_F 0.15915494309189533577f
#define MAGIC_F   12582912.0f            // 1.5 * 2^23

// Torus logmap, all fma-pipe (magic-number round; |x/2pi| < 2.2 << 2^22).
__device__ __forceinline__ float wrapf(float x) {
    float y = fmaf(x, INV_2PI_F, MAGIC_F);
    float k = __fadd_rn(y, -MAGIC_F);
    return fmaf(-k, TWO_PI_F, x);
}

__device__ __forceinline__ uint32_t smem_u32(const void* p) {
    uint32_t a;
    asm("{ .reg .u64 t; cvta.to.shared.u64 t, %1; cvt.u32.u64 %0, t; }"
        : "=r"(a) : "l"(p));
    return a;
}

__global__ __launch_bounds__(BLOCK) __cluster_dims__(CLUSTER, 1, 1)
void arp_tma_kernel(const float* __restrict__ g,
                    const float* __restrict__ ar_phi,
                    const float* __restrict__ ar_eta,
                    const float* __restrict__ ar_c,
                    float* __restrict__ out) {
    extern __shared__ char smem[];
    float* stage        = reinterpret_cast<float*>(smem);
    float (*sred)[8]    = reinterpret_cast<float (*)[8]>(smem + OFF_SRED);
    float (*slots)[3]   = reinterpret_cast<float (*)[3]>(smem + OFF_SLOTS);
    const uint32_t mbar = smem_u32(smem + OFF_MBAR);

    const int tid = threadIdx.x;
    const int m   = blockIdx.x / CLUSTER;
    uint32_t rank;
    asm("mov.u32 %0, %%cluster_ctarank;" : "=r"(rank));

    // ---- mbarrier init, then one bulk async copy of this CTA's 2 contiguous
    // sample-rows (48KB). TMA engine holds the in-flight bytes: chip-wide
    // ~12MB queued at once -> covers BW*latency, unlike the LDG path.
    if (tid == 0) {
        asm volatile("mbarrier.init.shared.b64 [%0], 1;" :: "r"(mbar) : "memory");
    }
    __syncthreads();
    if (tid == 0) {
        asm volatile("mbarrier.arrive.expect_tx.shared.b64 _, [%0], %1;"
                     :: "r"(mbar), "r"((uint32_t)STAGE_BYTES) : "memory");
        const float* src = g + (size_t)(m * N_SAMP + (int)rank * SPC) * ROW_ELEMS;
        asm volatile(
            "cp.async.bulk.shared::cluster.global.mbarrier::complete_tx::bytes "
            "[%0], [%1], %2, [%3];"
            :: "r"(smem_u32(stage)), "l"(src), "r"((uint32_t)STAGE_BYTES),
               "r"(mbar) : "memory");
    }

    // Small params while the copy flies (L1-cached broadcast loads).
    float ph[3][3], cc[3];
#pragma unroll
    for (int d = 0; d < 3; d++) {
        ph[d][0] = __ldg(&ar_phi[d * 3 + 0]);
        ph[d][1] = __ldg(&ar_phi[d * 3 + 1]);
        ph[d][2] = __ldg(&ar_phi[d * 3 + 2]);
        cc[d]    = __ldg(&ar_c[d]);
    }

    // Wait for the bulk copy (parity 0; SMEM is fresh each launch).
    {
        uint32_t done;
        asm volatile(
            "{\n\t.reg .pred p;\n\t"
            "mbarrier.try_wait.parity.acquire.cta.shared::cta.b64 p, [%1], 0;\n\t"
            "selp.b32 %0, 1, 0, p;\n\t}"
            : "=r"(done) : "r"(mbar) : "memory");
        if (!done) {
            asm volatile(
                "{\n\t.reg .pred P1;\n\t"
                "W%=:\n\t"
                "mbarrier.try_wait.parity.acquire.cta.shared::cta.b64 P1, [%0], 0, 0x989680;\n\t"
                "@P1 bra.uni D%=;\n\t"
                "bra.uni W%=;\n\t"
                "D%=:\n\t}"
                :: "r"(mbar) : "memory");
        }
    }

    // ---- Compute from SMEM: thread owns t-window [t0, t0+8) of each sample.
    // 9 LDS.128 per sample (lane stride 96B -> only 2-way phase conflicts).
    const int t0   = tid * CHUNK;
    const int b4   = 6 * tid;                 // (3*t0)/4
    const bool full = (t0 + CHUNK <= TPRIME); // false only for tid 255

    float acc[3] = {0.f, 0.f, 0.f};
#pragma unroll
    for (int s = 0; s < SPC; s++) {
        const float4* s4 = reinterpret_cast<const float4*>(stage + s * ROW_ELEMS);
        float f[36];
#pragma unroll
        for (int k = 0; k < 9; k++) {
            int idx = b4 + k;
            if (idx > ROW_VEC4 - 1) idx = ROW_VEC4 - 1;   // tail clamp (unused)
            float4 v = s4[idx];
            f[4 * k + 0] = v.x; f[4 * k + 1] = v.y;
            f[4 * k + 2] = v.z; f[4 * k + 3] = v.w;
        }
#pragma unroll
        for (int d = 0; d < 3; d++) {
            float dx[CHUNK + 3];
#pragma unroll
            for (int j = 0; j < CHUNK + 3; j++)
                dx[j] = wrapf(f[3 * (j + 1) + d] - f[3 * j + d]);
            float ss = 0.f;
            if (full) {
#pragma unroll
                for (int j = 0; j < CHUNK; j++) {
                    float dyv = dx[j + 3] - (ph[d][0] * dx[j + 2]
                                           + ph[d][1] * dx[j + 1]
                                           + ph[d][2] * dx[j]);
                    float u = dyv - cc[d];
                    ss = fmaf(u, u, ss);
                }
            } else {
#pragma unroll
                for (int j = 0; j < CHUNK; j++) {
                    float dyv = dx[j + 3] - (ph[d][0] * dx[j + 2]
                                           + ph[d][1] * dx[j + 1]
                                           + ph[d][2] * dx[j]);
                    float u = dyv - cc[d];
                    if (t0 + j < TPRIME) ss = fmaf(u, u, ss);
                }
            }
            acc[d] += ss;
        }
    }

    // ---- Warp reduce, then 8-warp fold.
#pragma unroll
    for (int off = 16; off; off >>= 1)
#pragma unroll
        for (int d = 0; d < 3; d++)
            acc[d] += __shfl_xor_sync(0xffffffffu, acc[d], off);

    const int lane = tid & 31;
    const int warp = tid >> 5;
    if (lane == 0)
#pragma unroll
        for (int d = 0; d < 3; d++) sred[d][warp] = acc[d];
    __syncthreads();

    // ---- tid0 pushes this CTA's 3 sums into the LEADER CTA's slots via DSMEM.
    if (tid == 0) {
        float S[3];
#pragma unroll
        for (int d = 0; d < 3; d++) {
            float v = sred[d][0];
#pragma unroll
            for (int w = 1; w < BLOCK / 32; w++) v += sred[d][w];
            S[d] = v;
        }
        uint32_t laddr = smem_u32(&slots[rank][0]);   // same layout in every CTA
        uint32_t raddr;
        asm volatile("mapa.shared::cluster.u32 %0, %1, %2;"
                     : "=r"(raddr) : "r"(laddr), "r"(0u));   // -> leader (rank 0)
#pragma unroll
        for (int d = 0; d < 3; d++)
            asm volatile("st.shared::cluster.f32 [%0], %1;"
                         :: "r"(raddr + 4u * d), "f"(S[d]) : "memory");
    }

    asm volatile("barrier.cluster.arrive.aligned;" ::: "memory");
    asm volatile("barrier.cluster.wait.aligned;" ::: "memory");

    // ---- Leader CTA: fold 8 ranks + closed-form winding constant.
    //   sum_{k=-5..5} collapses (sum k = 0, sum k^2 = 110) per (t,d) to:
    //   -5.5*u^2/var - 220*pi^2/var - 11*log(e) - 5.5*log(2*pi).
    if (rank == 0 && tid == 0) {
        float res = 0.f;
#pragma unroll
        for (int d = 0; d < 3; d++) {
            float Sd = 0.f;
#pragma unroll
            for (int r = 0; r < CLUSTER; r++) Sd += slots[r][d];
            float e   = fabsf(ar_eta[d]);            // scale = sqrt(eta^2)
            float var = e * e;
            float C = -220.f * (PI_F * PI_F) / var - 11.f * logf(e)
                      - 5.5f * logf(TWO_PI_F);
            res += -5.5f * Sd / var + (float)(N_SAMP * TPRIME) * C;
        }
        out[m] = res;
    }
}

extern "C" void kernel_launch(void* const* d_in, const int* in_sizes, int n_in,
                              void* d_out, int out_size) {
    const float* g      = (const float*)d_in[0];
    const float* ar_phi = (const float*)d_in[1];
    const float* ar_eta = (const float*)d_in[2];
    const float* ar_c   = (const float*)d_in[3];
    float* out = (float*)d_out;

    // Host-side attribute set (not a stream op; safe under graph capture).
    cudaFuncSetAttribute(arp_tma_kernel,
                         cudaFuncAttributeMaxDynamicSharedMemorySize, SMEM_TOTAL);
    arp_tma_kernel<<<GRID, BLOCK, SMEM_TOTAL>>>(g, ar_phi, ar_eta, ar_c, out);
}